// round 15
// baseline (speedup 1.0000x reference)
#include <cuda_runtime.h>
#include <math.h>

#define Bn 32
#define Qn 2000
#define Gn 64
#define Cn 80
#define LISTN 16

// Scratch
__device__ float g_costT[Bn * Gn * Qn];            // [b][g][q]
__device__ float g_iouT [Bn * Gn * Qn];            // [b][g][q]
__device__ int   g_gmin [Bn * Qn];                 // first argmin over g of cost row
__device__ int   g_list [Bn * Gn * LISTN];         // per-gt smallest-cost q ids, sorted; -1 = unknown tail
__device__ int   g_selk [Bn * Gn];                 // dynamic k per gt
__device__ unsigned long long g_match[Bn * Qn];    // final match bitmask per query

// ordered-float transforms (ascending order preserving)
__device__ __forceinline__ unsigned int ordf(float f) {
    unsigned int u = __float_as_uint(f);
    return (u & 0x80000000u) ? ~u : (u | 0x80000000u);
}
__device__ __forceinline__ float unordf(unsigned int o) {
    unsigned int u = (o & 0x80000000u) ? (o ^ 0x80000000u) : ~o;
    return __uint_as_float(u);
}

// ---------------------------------------------------------------------------
// Stage A: pairwise cost + iou + row argmin. (unchanged)
// ---------------------------------------------------------------------------
__global__ __launch_bounds__(128) void stageA(
        const float* __restrict__ logits,   // [B,Q,C]
        const float* __restrict__ boxes,    // [B,Q,4]
        const int*   __restrict__ gtcls,    // [B,G]
        const float* __restrict__ gtbox,    // [B,G,4]
        const float* __restrict__ szout,    // [B,4]
        const float* __restrict__ sztgt)    // [B,G,4]
{
    int b = blockIdx.x;

    __shared__ float4 s_box[Gn];
    __shared__ float4 s_cbb[Gn];
    __shared__ float4 s_tn[Gn];
    __shared__ float  s_area[Gn];
    __shared__ int    s_cls[Gn];
    __shared__ int    s_ord[Gn];

    if (threadIdx.x < Gn) {
        int g = threadIdx.x;
        const float* gb = gtbox + (size_t)(b * Gn + g) * 4;
        float gx1 = gb[0], gy1 = gb[1], gx2 = gb[2], gy2 = gb[3];
        s_box[g] = make_float4(gx1, gy1, gx2, gy2);
        s_area[g] = (gx2 - gx1) * (gy2 - gy1);
        float gcx = (gx1 + gx2) * 0.5f, gcy = (gy1 + gy2) * 0.5f;
        float gw = gx2 - gx1, gh = gy2 - gy1;
        s_cbb[g] = make_float4(gcx - 2.5f * gw, gcx + 2.5f * gw,
                               gcy - 2.5f * gh, gcy + 2.5f * gh);
        const float* tz = sztgt + (size_t)(b * Gn + g) * 4;
        s_tn[g] = make_float4(gx1 / tz[0], gy1 / tz[1], gx2 / tz[2], gy2 / tz[3]);
        s_cls[g] = gtcls[b * Gn + g];
    }
    __syncthreads();
    if (threadIdx.x < Gn) {
        int g = threadIdx.x;
        int c = s_cls[g];
        int rank = 0;
        for (int g2 = 0; g2 < Gn; g2++) {
            int c2 = s_cls[g2];
            rank += (c2 < c) || (c2 == c && g2 < g);
        }
        s_ord[rank] = g;
    }
    __syncthreads();

    int q = blockIdx.y * blockDim.x + threadIdx.x;
    if (q >= Qn) return;

    const float* bp = boxes + (size_t)(b * Qn + q) * 4;
    float x1 = bp[0], y1 = bp[1], x2 = bp[2], y2 = bp[3];
    float cx = (x1 + x2) * 0.5f, cy = (y1 + y2) * 0.5f;
    float areaA = (x2 - x1) * (y2 - y1);

    unsigned long long ibcMask = 0ull;
    bool anyIB = false, anyIC = false;
    for (int g = 0; g < Gn; g++) {
        float4 bx = s_box[g];
        bool ib = (cx > bx.x) && (cx < bx.z) && (cy > bx.y) && (cy < bx.w);
        float4 cb = s_cbb[g];
        bool icf = (cx > cb.x) && (cx < cb.y) && (cy > cb.z) && (cy < cb.w);
        anyIB |= ib; anyIC |= icf;
        if (ib && icf) ibcMask |= 1ull << g;
    }
    float fgpen = (anyIB || anyIC) ? 0.f : 1e4f;

    float so0 = szout[b * 4], so1 = szout[b * 4 + 1], so2 = szout[b * 4 + 2], so3 = szout[b * 4 + 3];
    float nx1 = x1 / so0, ny1 = y1 / so1, nx2 = x2 / so2, ny2 = y2 / so3;
    const float* lr = logits + (size_t)(b * Qn + q) * Cn;

    float* costOut = g_costT + (size_t)b * Gn * Qn;
    float* iouOut  = g_iouT  + (size_t)b * Gn * Qn;

    float best = 3.4e38f; int bidx = 0x7fffffff;
    int prevc = -1;
    float ccost = 0.f;
    for (int idx = 0; idx < Gn; idx++) {
        int g = s_ord[idx];
        int c = s_cls[g];
        if (c != prevc) {           // uniform across warp
            float p = lr[c];
            float pos = 0.25f * (1.f - p) * (1.f - p) * (-__logf(p + 1e-8f));
            float neg = 0.75f * p * p * (-__logf(1.f - p + 1e-8f));
            ccost = pos - neg;
            prevc = c;
        }

        float4 bx = s_box[g];
        float ix1 = fmaxf(x1, bx.x), iy1 = fmaxf(y1, bx.y);
        float ix2 = fminf(x2, bx.z), iy2 = fminf(y2, bx.w);
        float iw = fmaxf(ix2 - ix1, 0.f), ih = fmaxf(iy2 - iy1, 0.f);
        float inter = iw * ih;
        float uni = areaA + s_area[g] - inter;
        float iou = inter / uni;                    // exact: feeds floor(top5 sum)
        float ex1 = fminf(x1, bx.x), ey1 = fminf(y1, bx.y);
        float ex2 = fmaxf(x2, bx.z), ey2 = fmaxf(y2, bx.w);
        float ew = fmaxf(ex2 - ex1, 0.f), eh = fmaxf(ey2 - ey1, 0.f);
        float areaC = ew * eh;
        float giou = iou - __fdividef(areaC - uni, areaC);   // cost-only

        float4 tn = s_tn[g];
        float cb = fabsf(nx1 - tn.x) + fabsf(ny1 - tn.y) +
                   fabsf(nx2 - tn.z) + fabsf(ny2 - tn.w);

        bool inbc = (ibcMask >> g) & 1ull;
        float cost = 5.f * cb + 2.f * ccost + 2.f * (-giou) + (inbc ? 0.f : 100.f) + fgpen;
        costOut[(size_t)g * Qn + q] = cost;
        iouOut [(size_t)g * Qn + q] = iou;
        if (cost < best || (cost == best && g < bidx)) { best = cost; bidx = g; }
    }
    g_gmin[b * Qn + q] = bidx;
}

// ---------------------------------------------------------------------------
// Stage Zero: zero g_match (offloaded from B5; also shifts B5 to launch #4)
// ---------------------------------------------------------------------------
__global__ __launch_bounds__(256) void stageZero()
{
    int i = blockIdx.x * 256 + threadIdx.x;
    if (i < Bn * Qn) g_match[i] = 0ull;
}

// ---------------------------------------------------------------------------
// Stage Sel: one WARP per (b,g); 4x-unrolled stream + register merge
// ---------------------------------------------------------------------------
__device__ __forceinline__ unsigned long long warpMinBfly(unsigned long long v) {
    for (int off = 16; off; off >>= 1) {
        unsigned long long o = __shfl_xor_sync(0xffffffffu, v, off);
        if (o < v) v = o;
    }
    return v;
}
__device__ __forceinline__ unsigned long long warpOr64(unsigned long long v) {
    unsigned lo = __reduce_or_sync(0xffffffffu, (unsigned)v);
    unsigned hi = __reduce_or_sync(0xffffffffu, (unsigned)(v >> 32));
    return ((unsigned long long)hi << 32) | lo;
}

#define INS5(k) if ((k) < a4) { a4 = (k); \
    if (a4 < a3) { unsigned long long t = a3; a3 = a4; a4 = t; } \
    if (a3 < a2) { unsigned long long t = a2; a2 = a3; a3 = t; } \
    if (a2 < a1) { unsigned long long t = a1; a1 = a2; a2 = t; } \
    if (a1 < a0) { unsigned long long t = a0; a0 = a1; a1 = t; } }

#define INS8(k) if ((k) < c7) { c7 = (k); \
    if (c7 < c6) { unsigned long long t = c6; c6 = c7; c7 = t; } \
    if (c6 < c5) { unsigned long long t = c5; c5 = c6; c6 = t; } \
    if (c5 < c4) { unsigned long long t = c4; c4 = c5; c5 = t; } \
    if (c4 < c3) { unsigned long long t = c3; c3 = c4; c4 = t; } \
    if (c3 < c2) { unsigned long long t = c2; c2 = c3; c3 = t; } \
    if (c2 < c1) { unsigned long long t = c1; c1 = c2; c2 = t; } \
    if (c1 < c0) { unsigned long long t = c0; c0 = c1; c1 = t; } }

__global__ __launch_bounds__(256) void stageSel()
{
    int task = blockIdx.x * 8 + (threadIdx.x >> 5);    // b*Gn + g
    int lane = threadIdx.x & 31;
    const unsigned long long SENT = ~0ull;

    const float* ic = g_iouT  + (size_t)task * Qn;
    const float* cc = g_costT + (size_t)task * Qn;

    unsigned long long a0 = SENT, a1 = SENT, a2 = SENT, a3 = SENT, a4 = SENT;
    unsigned long long c0 = SENT, c1 = SENT, c2 = SENT, c3 = SENT,
                       c4 = SENT, c5 = SENT, c6 = SENT, c7 = SENT;

    int q = lane;
    for (; q + 96 < Qn; q += 128) {
        float i0 = ic[q], i1 = ic[q + 32], i2 = ic[q + 64], i3 = ic[q + 96];
        float v0 = cc[q], v1 = cc[q + 32], v2 = cc[q + 64], v3 = cc[q + 96];
        unsigned long long k;
        k = ((unsigned long long)(~ordf(i0)) << 32) | (unsigned)q;        INS5(k);
        k = ((unsigned long long)(~ordf(i1)) << 32) | (unsigned)(q + 32); INS5(k);
        k = ((unsigned long long)(~ordf(i2)) << 32) | (unsigned)(q + 64); INS5(k);
        k = ((unsigned long long)(~ordf(i3)) << 32) | (unsigned)(q + 96); INS5(k);
        k = ((unsigned long long)ordf(v0) << 32) | (unsigned)q;           INS8(k);
        k = ((unsigned long long)ordf(v1) << 32) | (unsigned)(q + 32);    INS8(k);
        k = ((unsigned long long)ordf(v2) << 32) | (unsigned)(q + 64);    INS8(k);
        k = ((unsigned long long)ordf(v3) << 32) | (unsigned)(q + 96);    INS8(k);
    }
    for (; q < Qn; q += 32) {
        unsigned long long ki = ((unsigned long long)(~ordf(ic[q])) << 32) | (unsigned)q;
        INS5(ki);
        unsigned long long kc = ((unsigned long long)ordf(cc[q]) << 32) | (unsigned)q;
        INS8(kc);
    }

    float sum = 0.f;
    for (int p = 0; p < 5; p++) {
        unsigned long long m = warpMinBfly(a0);
        sum += unordf(~(unsigned int)(m >> 32));
        if (a0 == m) { a0 = a1; a1 = a2; a2 = a3; a3 = a4; a4 = SENT; }
    }
    int k = (int)sum;          // truncating cast, as in the reference
    if (k < 1) k = 1;
    if (k > 5) k = 5;
    if (lane == 0) g_selk[task] = k;

    int ptr = 0;
    bool bad = false;
    for (int p = 0; p < LISTN; p++) {
        bad |= (__any_sync(0xffffffffu, ptr == 8) != 0);
        unsigned long long m = warpMinBfly(c0);
        if (lane == 0) g_list[task * LISTN + p] = bad ? -1 : (int)(unsigned int)(m & 0xffffffffu);
        if (!bad && c0 == m) {
            c0 = c1; c1 = c2; c2 = c3; c3 = c4; c4 = c5; c5 = c6; c6 = c7; c7 = SENT;
            ptr++;
        }
    }
}

// ---------------------------------------------------------------------------
// Stage B5: one warp per image; O(picks) iterations.
// NEW: fast exact fallback. Ranges are disjoint (cost < ~1.02e4, any
// penalized row >= 1e5-30), so the reference argmin over cost+pen is always
// on a penk==0 row when one exists; during the pick phase penk==0 <=>
// not listed at iteration start. Fallback = min (cost,q) over unlisted rows,
// no penalty adds. Slow exact path kept under the (impossible) all-listed guard.
// ---------------------------------------------------------------------------
__global__ __launch_bounds__(32) void stageB5(float* __restrict__ out)
{
    int b = blockIdx.x;
    int lane = threadIdx.x;
    const unsigned long long SENT = ~0ull;
    const unsigned FULL = 0xffffffffu;

    __shared__ unsigned long long s_m[Qn];          // match bitmask per query
    __shared__ int                s_listed[Qn];
    __shared__ signed char        s_stamp[Qn];      // append iteration; -1 initial
    __shared__ unsigned short     s_ls[Gn * LISTN]; // per-gt sorted lists (0xFFFF = unknown)
    __shared__ unsigned short     s_list[2048];     // compact matched rows (append-only)
    __shared__ unsigned short     s_fpick[Gn];
    __shared__ unsigned long long s_gkey[Gn];
    __shared__ int                s_n;

    const float* costB = g_costT + (size_t)b * Gn * Qn;
    const int*   listB = g_list + b * Gn * LISTN;
    const int*   gminB = g_gmin + b * Qn;

    for (int q = lane; q < Qn; q += 32) { s_m[q] = 0ull; s_listed[q] = 0; }
    for (int i = lane; i < Gn * LISTN; i += 32) {
        int q = listB[i];
        s_ls[i] = (q >= 0) ? (unsigned short)q : (unsigned short)0xFFFF;
    }
    if (lane == 0) s_n = 0;
    int k0 = g_selk[b * Gn + lane];
    int k1 = g_selk[b * Gn + lane + 32];
    __syncwarp();

    // initial picks
    for (int p = 0; p < k0; p++) atomicOr(&s_m[s_ls[lane * LISTN + p]], 1ull << lane);
    for (int p = 0; p < k1; p++) atomicOr(&s_m[s_ls[(lane + 32) * LISTN + p]], 1ull << (lane + 32));
    __syncwarp();

    // append initial rows, stamp = -1
    for (int j = 0; j < 2; j++) {
        int g = lane + j * 32;
        int kk = j ? k1 : k0;
        for (int p = 0; p < kk; p++) {
            int q = s_ls[g * LISTN + p];
            if (atomicExch(&s_listed[q], 1) == 0) {
                int i = atomicAdd(&s_n, 1);
                s_list[i] = (unsigned short)q;
                s_stamp[q] = (signed char)-1;
            }
        }
    }
    __syncwarp();

    // initial dedup + initial mg
    unsigned long long mg = 0ull;
    {
        int n = s_n;
        for (int i = lane; i < n; i += 32) {
            int q = s_list[i];
            unsigned long long m = s_m[q];
            if (__popcll(m) > 1) { m = 1ull << gminB[q]; s_m[q] = m; }
            mg |= m;
        }
        mg = warpOr64(mg);
    }
    __syncwarp();

    // bounded force-match loop
    int Tfin = Gn - 1;
    for (int t = 0; t < Gn; t++) {
        unsigned long long unm = ~mg;
        if (unm == 0ull) { Tfin = t - 1; break; }

        // walk picks: first UNLISTED entry (== penk==0) per unmatched gt
        int pq0 = -1, pq1 = -1;
        for (int j = 0; j < 2; j++) {
            int g = lane + j * 32;
            int pq = -1;
            if ((unm >> g) & 1ull) {
                pq = -2;
                for (int p = 0; p < LISTN; p++) {
                    unsigned short qq = s_ls[g * LISTN + p];
                    if (qq == 0xFFFF) break;                 // unknown tail -> fallback
                    if (!s_listed[qq]) { pq = (int)qq; break; }
                }
                if (pq >= 0) atomicOr(&s_m[pq], 1ull << g);
            }
            if (j == 0) pq0 = pq; else pq1 = pq;
        }

        // fallback
        int nfb = 0;
        bool relist = false;
        if (__any_sync(FULL, (pq0 == -2) || (pq1 == -2))) {
            unsigned m0 = __ballot_sync(FULL, pq0 == -2);
            unsigned m1 = __ballot_sync(FULL, pq1 == -2);
            unsigned long long fb = ((unsigned long long)m1 << 32) | m0;
            bool fast = (s_n < Qn);                         // always true in practice
            while (fb) {
                int g = __ffsll((long long)fb) - 1;
                fb &= fb - 1;
                const float* cg = costB + (size_t)g * Qn;
                unsigned long long bk = SENT;
                if (fast) {
                    // exact: argmin over penk==0 (= unlisted) rows at bare cost
                    for (int qq = lane; qq < Qn; qq += 32) {
                        if (!s_listed[qq]) {
                            unsigned long long key = ((unsigned long long)ordf(cg[qq]) << 32) | (unsigned)qq;
                            if (key < bk) bk = key;
                        }
                    }
                } else {
                    // exact slow path (unreachable in practice)
                    for (int qq = lane; qq < Qn; qq += 32) {
                        float v = cg[qq];
                        if (s_listed[qq]) {
                            int k = t - (int)s_stamp[qq];
                            for (int i = 0; i < k; i++) v += 1e5f;
                        }
                        unsigned long long key = ((unsigned long long)ordf(v) << 32) | (unsigned)qq;
                        if (key < bk) bk = key;
                    }
                }
                bk = warpMinBfly(bk);
                int qq = (int)(unsigned)(bk & 0xffffffffu);
                if (!fast && s_listed[qq]) relist = true;
                if (lane == 0) { s_m[qq] |= 1ull << g; s_fpick[nfb] = (unsigned short)qq; }
                nfb++;
            }
        }
        __syncwarp();

        // process picks: dedup, contribute to mg, append
        unsigned long long contrib = 0ull;
        for (int j = 0; j < 3; j++) {
            int pq;
            if (j == 0) pq = pq0;
            else if (j == 1) pq = pq1;
            else pq = (lane < nfb) ? (int)s_fpick[lane] : -1;
            if (j == 2 && lane + 32 < nfb) {
                int q2 = (int)s_fpick[lane + 32];
                unsigned long long m2 = s_m[q2];
                unsigned long long nm2 = (__popcll(m2) > 1) ? (1ull << gminB[q2]) : m2;
                if (nm2 != m2) s_m[q2] = nm2;
                contrib |= nm2;
                if (atomicExch(&s_listed[q2], 1) == 0) {
                    int i = atomicAdd(&s_n, 1);
                    s_list[i] = (unsigned short)q2;
                    s_stamp[q2] = (signed char)t;
                }
            }
            if (pq >= 0) {
                unsigned long long m = s_m[pq];
                unsigned long long nm = (__popcll(m) > 1) ? (1ull << gminB[pq]) : m;
                if (nm != m) s_m[pq] = nm;
                contrib |= nm;
                if (atomicExch(&s_listed[pq], 1) == 0) {
                    int i = atomicAdd(&s_n, 1);
                    s_list[i] = (unsigned short)pq;
                    s_stamp[pq] = (signed char)t;
                }
            }
        }
        contrib = warpOr64(contrib);
        __syncwarp();

        if (!__any_sync(FULL, relist)) {
            mg |= contrib;
        } else {
            unsigned long long m2 = 0ull;
            int n = s_n;
            for (int i = lane; i < n; i += 32) m2 |= s_m[s_list[i]];
            mg = warpOr64(m2);
        }
        __syncwarp();
    }

    // persist match bitmasks (g_match pre-zeroed by stageZero)
    unsigned long long* gm = g_match + b * Qn;
    int n = s_n;
    for (int i = lane; i < n; i += 32) { int q = s_list[i]; gm[q] = s_m[q]; }

    // matched_query_id: per-gt min (final penalized cost, q) over matched rows
    s_gkey[lane] = SENT; s_gkey[lane + 32] = SENT;
    __syncwarp();
    for (int i = lane; i < n; i += 32) {
        int q = s_list[i];
        unsigned long long m = s_m[q];                      // popc == 1 post-dedup
        int g = __ffsll((long long)m) - 1;
        float v = costB[(size_t)g * Qn + q];
        int k = Tfin - (int)s_stamp[q];
        for (int tt = 0; tt < k; tt++) v += 1e5f;
        unsigned long long key = ((unsigned long long)ordf(v) << 32) | (unsigned)q;
        atomicMin(&s_gkey[g], key);
    }
    __syncwarp();
    float* outI = out + (size_t)Bn * Qn * Gn + (size_t)b * Gn;
    for (int j = 0; j < 2; j++) {
        int g = lane + j * 32;
        unsigned long long key = s_gkey[g];
        outI[g] = (key == SENT) ? 0.f : (float)(unsigned)(key & 0xffffffffu);
    }
}

// ---------------------------------------------------------------------------
// Stage Out: expand bitmask to [B,Q,G] float matrix, float4 stores
// ---------------------------------------------------------------------------
__global__ __launch_bounds__(256) void stageOut(float* __restrict__ out)
{
    int idx = blockIdx.x * 256 + threadIdx.x;
    int i = idx * 4;
    int b = i / (Qn * Gn);
    int r = i - b * (Qn * Gn);
    int q = r >> 6, g = r & 63;
    unsigned long long m = g_match[b * Qn + q] >> g;
    float4 v;
    v.x = (m & 1ull) ? 1.f : 0.f;
    v.y = (m & 2ull) ? 1.f : 0.f;
    v.z = (m & 4ull) ? 1.f : 0.f;
    v.w = (m & 8ull) ? 1.f : 0.f;
    *reinterpret_cast<float4*>(out + i) = v;
}

// ---------------------------------------------------------------------------
// Launch order: A, Zero, Sel, B5, Out — B5 sits at app-launch #4, the slot
// the profiler captures (R12/R13 evidence), so this round yields B5's profile.
// ---------------------------------------------------------------------------
extern "C" void kernel_launch(void* const* d_in, const int* in_sizes, int n_in,
                              void* d_out, int out_size)
{
    const float* logits = (const float*)d_in[0];
    const float* boxes  = (const float*)d_in[1];
    const int*   gtc    = (const int*)  d_in[2];
    const float* gtb    = (const float*)d_in[3];
    const float* szo    = (const float*)d_in[4];
    const float* szt    = (const float*)d_in[5];

    dim3 gA(Bn, (Qn + 127) / 128);
    stageA<<<gA, 128>>>(logits, boxes, gtc, gtb, szo, szt);
    stageZero<<<(Bn * Qn + 255) / 256, 256>>>();
    stageSel<<<Bn * Gn / 8, 256>>>();
    stageB5<<<Bn, 32>>>((float*)d_out);
    stageOut<<<(Bn * Qn * Gn / 4) / 256, 256>>>((float*)d_out);
}

// round 16
// speedup vs baseline: 1.0708x; 1.0708x over previous
#include <cuda_runtime.h>
#include <math.h>

#define Bn 32
#define Qn 2000
#define Gn 64
#define Cn 80
#define LISTN 8

// Scratch
__device__ float g_costT[Bn * Gn * Qn];            // [b][g][q]
__device__ float g_iouT [Bn * Gn * Qn];            // [b][g][q]
__device__ int   g_gmin [Bn * Qn];                 // first argmin over g of cost row
__device__ int   g_list [Bn * Gn * LISTN];         // per-gt smallest-cost q ids, sorted; -1 = unknown tail
__device__ int   g_selk [Bn * Gn];                 // dynamic k per gt
__device__ unsigned long long g_match[Bn * Qn];    // final match bitmask per query

// ordered-float transforms (ascending order preserving)
__device__ __forceinline__ unsigned int ordf(float f) {
    unsigned int u = __float_as_uint(f);
    return (u & 0x80000000u) ? ~u : (u | 0x80000000u);
}
__device__ __forceinline__ float unordf(unsigned int o) {
    unsigned int u = (o & 0x80000000u) ? (o ^ 0x80000000u) : ~o;
    return __uint_as_float(u);
}

// ---------------------------------------------------------------------------
// Stage A: pairwise cost + iou + row argmin. (unchanged)
// ---------------------------------------------------------------------------
__global__ __launch_bounds__(128) void stageA(
        const float* __restrict__ logits,   // [B,Q,C]
        const float* __restrict__ boxes,    // [B,Q,4]
        const int*   __restrict__ gtcls,    // [B,G]
        const float* __restrict__ gtbox,    // [B,G,4]
        const float* __restrict__ szout,    // [B,4]
        const float* __restrict__ sztgt)    // [B,G,4]
{
    int b = blockIdx.x;

    __shared__ float4 s_box[Gn];
    __shared__ float4 s_cbb[Gn];
    __shared__ float4 s_tn[Gn];
    __shared__ float  s_area[Gn];
    __shared__ int    s_cls[Gn];
    __shared__ int    s_ord[Gn];

    if (threadIdx.x < Gn) {
        int g = threadIdx.x;
        const float* gb = gtbox + (size_t)(b * Gn + g) * 4;
        float gx1 = gb[0], gy1 = gb[1], gx2 = gb[2], gy2 = gb[3];
        s_box[g] = make_float4(gx1, gy1, gx2, gy2);
        s_area[g] = (gx2 - gx1) * (gy2 - gy1);
        float gcx = (gx1 + gx2) * 0.5f, gcy = (gy1 + gy2) * 0.5f;
        float gw = gx2 - gx1, gh = gy2 - gy1;
        s_cbb[g] = make_float4(gcx - 2.5f * gw, gcx + 2.5f * gw,
                               gcy - 2.5f * gh, gcy + 2.5f * gh);
        const float* tz = sztgt + (size_t)(b * Gn + g) * 4;
        s_tn[g] = make_float4(gx1 / tz[0], gy1 / tz[1], gx2 / tz[2], gy2 / tz[3]);
        s_cls[g] = gtcls[b * Gn + g];
    }
    __syncthreads();
    if (threadIdx.x < Gn) {
        int g = threadIdx.x;
        int c = s_cls[g];
        int rank = 0;
        for (int g2 = 0; g2 < Gn; g2++) {
            int c2 = s_cls[g2];
            rank += (c2 < c) || (c2 == c && g2 < g);
        }
        s_ord[rank] = g;
    }
    __syncthreads();

    int q = blockIdx.y * blockDim.x + threadIdx.x;
    if (q >= Qn) return;

    const float* bp = boxes + (size_t)(b * Qn + q) * 4;
    float x1 = bp[0], y1 = bp[1], x2 = bp[2], y2 = bp[3];
    float cx = (x1 + x2) * 0.5f, cy = (y1 + y2) * 0.5f;
    float areaA = (x2 - x1) * (y2 - y1);

    unsigned long long ibcMask = 0ull;
    bool anyIB = false, anyIC = false;
    for (int g = 0; g < Gn; g++) {
        float4 bx = s_box[g];
        bool ib = (cx > bx.x) && (cx < bx.z) && (cy > bx.y) && (cy < bx.w);
        float4 cb = s_cbb[g];
        bool icf = (cx > cb.x) && (cx < cb.y) && (cy > cb.z) && (cy < cb.w);
        anyIB |= ib; anyIC |= icf;
        if (ib && icf) ibcMask |= 1ull << g;
    }
    float fgpen = (anyIB || anyIC) ? 0.f : 1e4f;

    float so0 = szout[b * 4], so1 = szout[b * 4 + 1], so2 = szout[b * 4 + 2], so3 = szout[b * 4 + 3];
    float nx1 = x1 / so0, ny1 = y1 / so1, nx2 = x2 / so2, ny2 = y2 / so3;
    const float* lr = logits + (size_t)(b * Qn + q) * Cn;

    float* costOut = g_costT + (size_t)b * Gn * Qn;
    float* iouOut  = g_iouT  + (size_t)b * Gn * Qn;

    float best = 3.4e38f; int bidx = 0x7fffffff;
    int prevc = -1;
    float ccost = 0.f;
    for (int idx = 0; idx < Gn; idx++) {
        int g = s_ord[idx];
        int c = s_cls[g];
        if (c != prevc) {           // uniform across warp
            float p = lr[c];
            float pos = 0.25f * (1.f - p) * (1.f - p) * (-__logf(p + 1e-8f));
            float neg = 0.75f * p * p * (-__logf(1.f - p + 1e-8f));
            ccost = pos - neg;
            prevc = c;
        }

        float4 bx = s_box[g];
        float ix1 = fmaxf(x1, bx.x), iy1 = fmaxf(y1, bx.y);
        float ix2 = fminf(x2, bx.z), iy2 = fminf(y2, bx.w);
        float iw = fmaxf(ix2 - ix1, 0.f), ih = fmaxf(iy2 - iy1, 0.f);
        float inter = iw * ih;
        float uni = areaA + s_area[g] - inter;
        float iou = inter / uni;                    // exact: feeds floor(top5 sum)
        float ex1 = fminf(x1, bx.x), ey1 = fminf(y1, bx.y);
        float ex2 = fmaxf(x2, bx.z), ey2 = fmaxf(y2, bx.w);
        float ew = fmaxf(ex2 - ex1, 0.f), eh = fmaxf(ey2 - ey1, 0.f);
        float areaC = ew * eh;
        float giou = iou - __fdividef(areaC - uni, areaC);   // cost-only

        float4 tn = s_tn[g];
        float cb = fabsf(nx1 - tn.x) + fabsf(ny1 - tn.y) +
                   fabsf(nx2 - tn.z) + fabsf(ny2 - tn.w);

        bool inbc = (ibcMask >> g) & 1ull;
        float cost = 5.f * cb + 2.f * ccost + 2.f * (-giou) + (inbc ? 0.f : 100.f) + fgpen;
        costOut[(size_t)g * Qn + q] = cost;
        iouOut [(size_t)g * Qn + q] = iou;
        if (cost < best || (cost == best && g < bidx)) { best = cost; bidx = g; }
    }
    g_gmin[b * Qn + q] = bidx;
}

// ---------------------------------------------------------------------------
// Stage Sel: TWO warps per (b,g) — one streams iou (top-5), one streams cost
// (bottom-8 via depth-5 per-lane runs). No barriers, halved serial chains.
// ---------------------------------------------------------------------------
__device__ __forceinline__ unsigned long long warpMinBfly(unsigned long long v) {
    for (int off = 16; off; off >>= 1) {
        unsigned long long o = __shfl_xor_sync(0xffffffffu, v, off);
        if (o < v) v = o;
    }
    return v;
}
__device__ __forceinline__ unsigned long long warpOr64(unsigned long long v) {
    unsigned lo = __reduce_or_sync(0xffffffffu, (unsigned)v);
    unsigned hi = __reduce_or_sync(0xffffffffu, (unsigned)(v >> 32));
    return ((unsigned long long)hi << 32) | lo;
}

#define INS5(k) if ((k) < a4) { a4 = (k); \
    if (a4 < a3) { unsigned long long t = a3; a3 = a4; a4 = t; } \
    if (a3 < a2) { unsigned long long t = a2; a2 = a3; a3 = t; } \
    if (a2 < a1) { unsigned long long t = a1; a1 = a2; a2 = t; } \
    if (a1 < a0) { unsigned long long t = a0; a0 = a1; a1 = t; } }

__global__ __launch_bounds__(256) void stageSel()
{
    int w = threadIdx.x >> 5;                      // 8 warps -> 4 tasks x 2 roles
    int task = blockIdx.x * 4 + (w >> 1);          // b*Gn + g
    int role = w & 1;
    int lane = threadIdx.x & 31;
    const unsigned long long SENT = ~0ull;
    const unsigned FULL = 0xffffffffu;

    unsigned long long a0 = SENT, a1 = SENT, a2 = SENT, a3 = SENT, a4 = SENT;

    if (role) {
        // ---- iou warp: exact top-5, summed in extraction order (== jax top_k)
        const float* ic = g_iouT + (size_t)task * Qn;
        int q = lane;
        for (; q + 96 < Qn; q += 128) {
            float i0 = ic[q], i1 = ic[q + 32], i2 = ic[q + 64], i3 = ic[q + 96];
            unsigned long long k;
            k = ((unsigned long long)(~ordf(i0)) << 32) | (unsigned)q;        INS5(k);
            k = ((unsigned long long)(~ordf(i1)) << 32) | (unsigned)(q + 32); INS5(k);
            k = ((unsigned long long)(~ordf(i2)) << 32) | (unsigned)(q + 64); INS5(k);
            k = ((unsigned long long)(~ordf(i3)) << 32) | (unsigned)(q + 96); INS5(k);
        }
        for (; q < Qn; q += 32) {
            unsigned long long k = ((unsigned long long)(~ordf(ic[q])) << 32) | (unsigned)q;
            INS5(k);
        }
        float sum = 0.f;
        for (int p = 0; p < 5; p++) {
            unsigned long long m = warpMinBfly(a0);
            sum += unordf(~(unsigned int)(m >> 32));
            if (a0 == m) { a0 = a1; a1 = a2; a2 = a3; a3 = a4; a4 = SENT; }
        }
        int k = (int)sum;          // truncating cast, as in the reference
        if (k < 1) k = 1;
        if (k > 5) k = 5;
        if (lane == 0) g_selk[task] = k;
    } else {
        // ---- cost warp: bottom-8 from per-lane depth-5 runs.
        // First 5 entries always exact (a lane cannot exhaust depth 5 within
        // 5 rounds); entries 5..7 may be -1 (unknown tail -> B5 fallback).
        const float* cc = g_costT + (size_t)task * Qn;
        int q = lane;
        for (; q + 96 < Qn; q += 128) {
            float v0 = cc[q], v1 = cc[q + 32], v2 = cc[q + 64], v3 = cc[q + 96];
            unsigned long long k;
            k = ((unsigned long long)ordf(v0) << 32) | (unsigned)q;        INS5(k);
            k = ((unsigned long long)ordf(v1) << 32) | (unsigned)(q + 32); INS5(k);
            k = ((unsigned long long)ordf(v2) << 32) | (unsigned)(q + 64); INS5(k);
            k = ((unsigned long long)ordf(v3) << 32) | (unsigned)(q + 96); INS5(k);
        }
        for (; q < Qn; q += 32) {
            unsigned long long k = ((unsigned long long)ordf(cc[q]) << 32) | (unsigned)q;
            INS5(k);
        }
        int ptr = 0;
        bool bad = false;
        for (int p = 0; p < LISTN; p++) {
            bad |= (__any_sync(FULL, ptr == 5) != 0);
            unsigned long long m = warpMinBfly(a0);
            if (lane == 0) g_list[task * LISTN + p] = bad ? -1 : (int)(unsigned int)(m & 0xffffffffu);
            if (!bad && a0 == m) {
                a0 = a1; a1 = a2; a2 = a3; a3 = a4; a4 = SENT;
                ptr++;
            }
        }
    }
}

// ---------------------------------------------------------------------------
// Stage B5: one warp per image; O(picks) iterations, fast exact fallback.
// (R15-validated logic; LISTN=8, g_match zeroing folded back in.)
// ---------------------------------------------------------------------------
__global__ __launch_bounds__(32) void stageB5(float* __restrict__ out)
{
    int b = blockIdx.x;
    int lane = threadIdx.x;
    const unsigned long long SENT = ~0ull;
    const unsigned FULL = 0xffffffffu;

    __shared__ unsigned long long s_m[Qn];          // match bitmask per query
    __shared__ int                s_listed[Qn];
    __shared__ signed char        s_stamp[Qn];      // append iteration; -1 initial
    __shared__ unsigned short     s_ls[Gn * LISTN]; // per-gt sorted lists (0xFFFF = unknown)
    __shared__ unsigned short     s_list[2048];     // compact matched rows (append-only)
    __shared__ unsigned short     s_fpick[Gn];
    __shared__ unsigned long long s_gkey[Gn];
    __shared__ int                s_n;

    const float* costB = g_costT + (size_t)b * Gn * Qn;
    const int*   listB = g_list + b * Gn * LISTN;
    const int*   gminB = g_gmin + b * Qn;

    for (int q = lane; q < Qn; q += 32) { s_m[q] = 0ull; s_listed[q] = 0; }
    for (int i = lane; i < Gn * LISTN; i += 32) {
        int q = listB[i];
        s_ls[i] = (q >= 0) ? (unsigned short)q : (unsigned short)0xFFFF;
    }
    if (lane == 0) s_n = 0;
    int k0 = g_selk[b * Gn + lane];
    int k1 = g_selk[b * Gn + lane + 32];
    __syncwarp();

    // initial picks (first selk<=5 entries; always-valid head of the list)
    for (int p = 0; p < k0; p++) atomicOr(&s_m[s_ls[lane * LISTN + p]], 1ull << lane);
    for (int p = 0; p < k1; p++) atomicOr(&s_m[s_ls[(lane + 32) * LISTN + p]], 1ull << (lane + 32));
    __syncwarp();

    // append initial rows, stamp = -1
    for (int j = 0; j < 2; j++) {
        int g = lane + j * 32;
        int kk = j ? k1 : k0;
        for (int p = 0; p < kk; p++) {
            int q = s_ls[g * LISTN + p];
            if (atomicExch(&s_listed[q], 1) == 0) {
                int i = atomicAdd(&s_n, 1);
                s_list[i] = (unsigned short)q;
                s_stamp[q] = (signed char)-1;
            }
        }
    }
    __syncwarp();

    // initial dedup + initial mg
    unsigned long long mg = 0ull;
    {
        int n = s_n;
        for (int i = lane; i < n; i += 32) {
            int q = s_list[i];
            unsigned long long m = s_m[q];
            if (__popcll(m) > 1) { m = 1ull << gminB[q]; s_m[q] = m; }
            mg |= m;
        }
        mg = warpOr64(mg);
    }
    __syncwarp();

    // bounded force-match loop
    int Tfin = Gn - 1;
    for (int t = 0; t < Gn; t++) {
        unsigned long long unm = ~mg;
        if (unm == 0ull) { Tfin = t - 1; break; }

        // walk picks: first UNLISTED entry (== penk==0) per unmatched gt
        int pq0 = -1, pq1 = -1;
        for (int j = 0; j < 2; j++) {
            int g = lane + j * 32;
            int pq = -1;
            if ((unm >> g) & 1ull) {
                pq = -2;
                for (int p = 0; p < LISTN; p++) {
                    unsigned short qq = s_ls[g * LISTN + p];
                    if (qq == 0xFFFF) break;                 // unknown tail -> fallback
                    if (!s_listed[qq]) { pq = (int)qq; break; }
                }
                if (pq >= 0) atomicOr(&s_m[pq], 1ull << g);
            }
            if (j == 0) pq0 = pq; else pq1 = pq;
        }

        // fallback
        int nfb = 0;
        bool relist = false;
        if (__any_sync(FULL, (pq0 == -2) || (pq1 == -2))) {
            unsigned m0 = __ballot_sync(FULL, pq0 == -2);
            unsigned m1 = __ballot_sync(FULL, pq1 == -2);
            unsigned long long fb = ((unsigned long long)m1 << 32) | m0;
            bool fast = (s_n < Qn);                         // always true in practice
            while (fb) {
                int g = __ffsll((long long)fb) - 1;
                fb &= fb - 1;
                const float* cg = costB + (size_t)g * Qn;
                unsigned long long bk = SENT;
                if (fast) {
                    // exact: argmin over penk==0 (= unlisted) rows at bare cost
                    for (int qq = lane; qq < Qn; qq += 32) {
                        if (!s_listed[qq]) {
                            unsigned long long key = ((unsigned long long)ordf(cg[qq]) << 32) | (unsigned)qq;
                            if (key < bk) bk = key;
                        }
                    }
                } else {
                    // exact slow path (unreachable in practice)
                    for (int qq = lane; qq < Qn; qq += 32) {
                        float v = cg[qq];
                        if (s_listed[qq]) {
                            int k = t - (int)s_stamp[qq];
                            for (int i = 0; i < k; i++) v += 1e5f;
                        }
                        unsigned long long key = ((unsigned long long)ordf(v) << 32) | (unsigned)qq;
                        if (key < bk) bk = key;
                    }
                }
                bk = warpMinBfly(bk);
                int qq = (int)(unsigned)(bk & 0xffffffffu);
                if (!fast && s_listed[qq]) relist = true;
                if (lane == 0) { s_m[qq] |= 1ull << g; s_fpick[nfb] = (unsigned short)qq; }
                nfb++;
            }
        }
        __syncwarp();

        // process picks: dedup, contribute to mg, append
        unsigned long long contrib = 0ull;
        for (int j = 0; j < 3; j++) {
            int pq;
            if (j == 0) pq = pq0;
            else if (j == 1) pq = pq1;
            else pq = (lane < nfb) ? (int)s_fpick[lane] : -1;
            if (j == 2 && lane + 32 < nfb) {
                int q2 = (int)s_fpick[lane + 32];
                unsigned long long m2 = s_m[q2];
                unsigned long long nm2 = (__popcll(m2) > 1) ? (1ull << gminB[q2]) : m2;
                if (nm2 != m2) s_m[q2] = nm2;
                contrib |= nm2;
                if (atomicExch(&s_listed[q2], 1) == 0) {
                    int i = atomicAdd(&s_n, 1);
                    s_list[i] = (unsigned short)q2;
                    s_stamp[q2] = (signed char)t;
                }
            }
            if (pq >= 0) {
                unsigned long long m = s_m[pq];
                unsigned long long nm = (__popcll(m) > 1) ? (1ull << gminB[pq]) : m;
                if (nm != m) s_m[pq] = nm;
                contrib |= nm;
                if (atomicExch(&s_listed[pq], 1) == 0) {
                    int i = atomicAdd(&s_n, 1);
                    s_list[i] = (unsigned short)pq;
                    s_stamp[pq] = (signed char)t;
                }
            }
        }
        contrib = warpOr64(contrib);
        __syncwarp();

        if (!__any_sync(FULL, relist)) {
            mg |= contrib;
        } else {
            unsigned long long m2 = 0ull;
            int n = s_n;
            for (int i = lane; i < n; i += 32) m2 |= s_m[s_list[i]];
            mg = warpOr64(m2);
        }
        __syncwarp();
    }

    // persist match bitmasks (zeros first, then listed rows; warp-fenced)
    unsigned long long* gm = g_match + b * Qn;
    for (int q = lane; q < Qn; q += 32) gm[q] = 0ull;
    int n = s_n;
    __syncwarp();
    for (int i = lane; i < n; i += 32) { int q = s_list[i]; gm[q] = s_m[q]; }

    // matched_query_id: per-gt min (final penalized cost, q) over matched rows
    s_gkey[lane] = SENT; s_gkey[lane + 32] = SENT;
    __syncwarp();
    for (int i = lane; i < n; i += 32) {
        int q = s_list[i];
        unsigned long long m = s_m[q];                      // popc == 1 post-dedup
        int g = __ffsll((long long)m) - 1;
        float v = costB[(size_t)g * Qn + q];
        int k = Tfin - (int)s_stamp[q];
        for (int tt = 0; tt < k; tt++) v += 1e5f;
        unsigned long long key = ((unsigned long long)ordf(v) << 32) | (unsigned)q;
        atomicMin(&s_gkey[g], key);
    }
    __syncwarp();
    float* outI = out + (size_t)Bn * Qn * Gn + (size_t)b * Gn;
    for (int j = 0; j < 2; j++) {
        int g = lane + j * 32;
        unsigned long long key = s_gkey[g];
        outI[g] = (key == SENT) ? 0.f : (float)(unsigned)(key & 0xffffffffu);
    }
}

// ---------------------------------------------------------------------------
// Stage Out: expand bitmask to [B,Q,G] float matrix, float4 stores
// ---------------------------------------------------------------------------
__global__ __launch_bounds__(256) void stageOut(float* __restrict__ out)
{
    int idx = blockIdx.x * 256 + threadIdx.x;
    int i = idx * 4;
    int b = i / (Qn * Gn);
    int r = i - b * (Qn * Gn);
    int q = r >> 6, g = r & 63;
    unsigned long long m = g_match[b * Qn + q] >> g;
    float4 v;
    v.x = (m & 1ull) ? 1.f : 0.f;
    v.y = (m & 2ull) ? 1.f : 0.f;
    v.z = (m & 4ull) ? 1.f : 0.f;
    v.w = (m & 8ull) ? 1.f : 0.f;
    *reinterpret_cast<float4*>(out + i) = v;
}

// ---------------------------------------------------------------------------
extern "C" void kernel_launch(void* const* d_in, const int* in_sizes, int n_in,
                              void* d_out, int out_size)
{
    const float* logits = (const float*)d_in[0];
    const float* boxes  = (const float*)d_in[1];
    const int*   gtc    = (const int*)  d_in[2];
    const float* gtb    = (const float*)d_in[3];
    const float* szo    = (const float*)d_in[4];
    const float* szt    = (const float*)d_in[5];

    dim3 gA(Bn, (Qn + 127) / 128);
    stageA<<<gA, 128>>>(logits, boxes, gtc, gtb, szo, szt);
    stageSel<<<Bn * Gn / 4, 256>>>();          // 2 warps per (b,g) task
    stageB5<<<Bn, 32>>>((float*)d_out);
    stageOut<<<(Bn * Qn * Gn / 4) / 256, 256>>>((float*)d_out);
}